// round 2
// baseline (speedup 1.0000x reference)
#include <cuda_runtime.h>
#include <cuda_bf16.h>

#define VOCAB 10000
#define EMB   100
#define SEQ   80
#define BATCH 1024
#define UNITS 512
#define ZDIM  2048      // 4*UNITS
#define HSTR  1024      // Hcat row stride (h1 | h2)

// ---------------- device scratch (static, no allocations) ----------------
__device__ float g_EmbW1r[(size_t)VOCAB * ZDIM];   // emb@W1, gate-interleaved cols, b1 baked in (82MB)
__device__ float g_U1r [UNITS * ZDIM];             // U1 reordered
__device__ float g_Wcat[(2 * UNITS) * ZDIM];       // [W2;U2] reordered (K=1024)
__device__ float g_b2r [ZDIM];
__device__ float g_H0[(size_t)BATCH * HSTR];       // ping-pong hidden state (h1|h2)
__device__ float g_H1[(size_t)BATCH * HSTR];
__device__ float g_C1[(size_t)BATCH * UNITS];
__device__ float g_C2[(size_t)BATCH * UNITS];

// ---------------- helpers ----------------
__device__ __forceinline__ float sigm(float x) {
    return __fdividef(1.0f, 1.0f + __expf(-x));
}

// packed fp32x2 FMA (Blackwell): d = a*b + d, elementwise on 2 lanes
__device__ __forceinline__ void ffma2(unsigned long long& c, unsigned long long a, unsigned long long b) {
    asm("fma.rn.f32x2 %0, %1, %2, %0;" : "+l"(c) : "l"(a), "l"(b));
}

// ---------------- init ----------------
__global__ void zero_state() {
    int i = blockIdx.x * blockDim.x + threadIdx.x;
    if (i < BATCH * HSTR) { g_H0[i] = 0.0f; g_H1[i] = 0.0f; }
    if (i < BATCH * UNITS) { g_C1[i] = 0.0f; g_C2[i] = 0.0f; }
}

// gate-interleave reorder: newcol c -> source col (c&3)*UNITS + (c>>2)
__global__ void reorder_weights(const float* __restrict__ U1, const float* __restrict__ W2,
                                const float* __restrict__ U2, const float* __restrict__ b2) {
    int i = blockIdx.x * blockDim.x + threadIdx.x;
    if (i >= 2 * UNITS * ZDIM) return;
    int k = i / ZDIM, c = i % ZDIM;
    int src = (c & 3) * UNITS + (c >> 2);
    if (k < UNITS) {
        g_U1r[i]  = U1[k * ZDIM + src];
        g_Wcat[i] = W2[k * ZDIM + src];
    } else {
        g_Wcat[i] = U2[(k - UNITS) * ZDIM + src];
    }
    if (i < ZDIM) g_b2r[i] = b2[src];
}

// EmbW1r[v][c] = sum_e emb[v][e] * W1[e][srccol(c)] + b1[srccol(c)]
// BM=64 (vocab), BN=64 (zcols), BK=32, TM=TN=4, 256 threads
__global__ __launch_bounds__(256) void embw1_kernel(const float* __restrict__ emb,
                                                    const float* __restrict__ W1,
                                                    const float* __restrict__ b1) {
    __shared__ float Ae[32][65];
    __shared__ float Be[32][64];
    int tid = threadIdx.x;
    int tx = tid & 15, ty = tid >> 4;
    int vBase = blockIdx.y * 64, cBase = blockIdx.x * 64;

    float acc[4][4];
#pragma unroll
    for (int i = 0; i < 4; ++i)
#pragma unroll
        for (int j = 0; j < 4; ++j) acc[i][j] = 0.0f;

    for (int kt = 0; kt < 4; ++kt) {  // ceil(100/32)
        // A: 64 rows x 32 k
        {
            int vrow = tid >> 2;
            int k0 = (tid & 3) * 8;
            int v = vBase + vrow;
#pragma unroll
            for (int j = 0; j < 8; ++j) {
                int k = kt * 32 + k0 + j;
                float val = (k < EMB && v < VOCAB) ? emb[v * EMB + k] : 0.0f;
                Ae[k0 + j][vrow] = val;
            }
        }
        // B: 32 k x 64 cols (reordered source)
        {
            int krow = tid >> 3;
            int c0 = (tid & 7) * 8;
            int k = kt * 32 + krow;
#pragma unroll
            for (int j = 0; j < 8; ++j) {
                int c = cBase + c0 + j;
                int src = (c & 3) * UNITS + (c >> 2);
                Be[krow][c0 + j] = (k < EMB) ? W1[k * ZDIM + src] : 0.0f;
            }
        }
        __syncthreads();
#pragma unroll
        for (int kk = 0; kk < 32; ++kk) {
            float a[4], b[4];
#pragma unroll
            for (int i = 0; i < 4; ++i) a[i] = Ae[kk][ty * 4 + i];
#pragma unroll
            for (int j = 0; j < 4; ++j) b[j] = Be[kk][tx * 4 + j];
#pragma unroll
            for (int i = 0; i < 4; ++i)
#pragma unroll
                for (int j = 0; j < 4; ++j) acc[i][j] = fmaf(a[i], b[j], acc[i][j]);
        }
        __syncthreads();
    }
#pragma unroll
    for (int i = 0; i < 4; ++i) {
        int v = vBase + ty * 4 + i;
        if (v >= VOCAB) continue;
#pragma unroll
        for (int j = 0; j < 4; ++j) {
            int c = cBase + tx * 4 + j;
            int src = (c & 3) * UNITS + (c >> 2);
            g_EmbW1r[(size_t)v * ZDIM + c] = acc[i][j] + b1[src];
        }
    }
}

// ---------------- per-timestep fused GEMM + LSTM cell ----------------
// C[1024, 2048] = A[1024, K] @ B[K, 2048], K=512 (layer1) or 1024 (layer2)
// BM=128, BN=128, BK=16, 256 threads, per-thread 8x8 via fp32x2 pairs.
__global__ __launch_bounds__(256) void lstm_step(const int* __restrict__ tokens, int t,
                                                 int ping, int layer) {
    __shared__ float  As[16][128];
    __shared__ float2 Bs[16][128];   // B duplicated {b,b} for packed FMA

    const float* Hp = ping ? g_H1 : g_H0;
    float*       Hc = ping ? g_H0 : g_H1;

    const float *A_lo, *A_hi, *Bw;
    float* Cst;
    int K, outOff;
    if (layer == 0) { A_lo = Hp; A_hi = Hp; Bw = g_U1r;  Cst = g_C1; K = 512;  outOff = 0; }
    else            { A_lo = Hc; A_hi = Hp; Bw = g_Wcat; Cst = g_C2; K = 1024; outOff = UNITS; }

    int tid = threadIdx.x;
    int tx = tid & 15, ty = tid >> 4;
    int rowTile = blockIdx.y * 128, colTile = blockIdx.x * 128;

    // loader lanes
    int arow = tid >> 1, ak = (tid & 1) * 8;           // A: 128 rows x 16k
    int brow = tid >> 4, bcol = (tid & 15) * 8;        // B: 16k x 128 cols

    unsigned long long acc[4][8];
#pragma unroll
    for (int mp = 0; mp < 4; ++mp)
#pragma unroll
        for (int j = 0; j < 8; ++j) acc[mp][j] = 0ULL;

    int nk = K >> 4;
    float4 pa0, pa1, pb0, pb1;

    // prefetch tile 0
    {
        int kg = 0 * 16 + ak;
        const float* Ab = (kg < 512) ? A_lo : A_hi;
        const float* ap = Ab + (size_t)(rowTile + arow) * HSTR + kg;
        pa0 = *(const float4*)ap; pa1 = *(const float4*)(ap + 4);
        const float* bp = Bw + (size_t)(0 * 16 + brow) * ZDIM + colTile + bcol;
        pb0 = *(const float4*)bp; pb1 = *(const float4*)(bp + 4);
    }

    for (int kt = 0; kt < nk; ++kt) {
        // commit prefetched tile to smem
        As[ak + 0][arow] = pa0.x; As[ak + 1][arow] = pa0.y;
        As[ak + 2][arow] = pa0.z; As[ak + 3][arow] = pa0.w;
        As[ak + 4][arow] = pa1.x; As[ak + 5][arow] = pa1.y;
        As[ak + 6][arow] = pa1.z; As[ak + 7][arow] = pa1.w;
        Bs[brow][bcol + 0] = make_float2(pb0.x, pb0.x);
        Bs[brow][bcol + 1] = make_float2(pb0.y, pb0.y);
        Bs[brow][bcol + 2] = make_float2(pb0.z, pb0.z);
        Bs[brow][bcol + 3] = make_float2(pb0.w, pb0.w);
        Bs[brow][bcol + 4] = make_float2(pb1.x, pb1.x);
        Bs[brow][bcol + 5] = make_float2(pb1.y, pb1.y);
        Bs[brow][bcol + 6] = make_float2(pb1.z, pb1.z);
        Bs[brow][bcol + 7] = make_float2(pb1.w, pb1.w);
        __syncthreads();

        if (kt + 1 < nk) {  // prefetch next tile while computing
            int kg = (kt + 1) * 16 + ak;
            const float* Ab = (kg < 512) ? A_lo : A_hi;
            const float* ap = Ab + (size_t)(rowTile + arow) * HSTR + kg;
            pa0 = *(const float4*)ap; pa1 = *(const float4*)(ap + 4);
            const float* bp = Bw + (size_t)((kt + 1) * 16 + brow) * ZDIM + colTile + bcol;
            pb0 = *(const float4*)bp; pb1 = *(const float4*)(bp + 4);
        }

#pragma unroll
        for (int kk = 0; kk < 16; ++kk) {
            unsigned long long a2[4], b2[8];
            const unsigned long long* apr = (const unsigned long long*)&As[kk][ty * 8];
#pragma unroll
            for (int mp = 0; mp < 4; ++mp) a2[mp] = apr[mp];
            const unsigned long long* bpr = (const unsigned long long*)&Bs[kk][tx * 8];
#pragma unroll
            for (int j = 0; j < 8; ++j) b2[j] = bpr[j];
#pragma unroll
            for (int mp = 0; mp < 4; ++mp)
#pragma unroll
                for (int j = 0; j < 8; ++j) ffma2(acc[mp][j], a2[mp], b2[j]);
        }
        __syncthreads();
    }

    // epilogue: z -> gates -> (c,h).  cols = u*4+g, thread owns 2 full units x 8 rows
    int colBase = colTile + tx * 8;
    int rowBase = rowTile + ty * 8;
    int uBase = colBase >> 2;
#pragma unroll
    for (int mp = 0; mp < 4; ++mp) {
#pragma unroll
        for (int half = 0; half < 2; ++half) {
            int row = rowBase + mp * 2 + half;
            float z[8];
#pragma unroll
            for (int j = 0; j < 8; ++j) {
                unsigned long long v = acc[mp][j];
                z[j] = half ? __uint_as_float((unsigned)(v >> 32)) : __uint_as_float((unsigned)v);
            }
            if (layer == 0) {
                int tok = tokens[row * SEQ + t];
                const float* add = g_EmbW1r + (size_t)tok * ZDIM + colBase;
#pragma unroll
                for (int j = 0; j < 8; ++j) z[j] += add[j];
            } else {
#pragma unroll
                for (int j = 0; j < 8; ++j) z[j] += g_b2r[colBase + j];
            }
#pragma unroll
            for (int uu = 0; uu < 2; ++uu) {
                float zi = z[uu * 4 + 0], zf = z[uu * 4 + 1];
                float zg = z[uu * 4 + 2], zo = z[uu * 4 + 3];
                int u = uBase + uu;
                float* cp = Cst + (size_t)row * UNITS + u;
                float cn = sigm(zf) * (*cp) + sigm(zi) * tanhf(zg);
                *cp = cn;
                Hc[(size_t)row * HSTR + outOff + u] = sigm(zo) * tanhf(cn);
            }
        }
    }
}

// ---------------- output head ----------------
__global__ void out_kernel(const float* __restrict__ Wout, const float* __restrict__ bout,
                           float* __restrict__ out, int ping) {
    const float* H = ping ? g_H1 : g_H0;
    int gwarp = (blockIdx.x * blockDim.x + threadIdx.x) >> 5;   // batch row
    int lane = threadIdx.x & 31;
    float s = 0.0f;
    for (int k = lane; k < UNITS; k += 32)
        s += H[(size_t)gwarp * HSTR + UNITS + k] * Wout[k];
#pragma unroll
    for (int off = 16; off; off >>= 1) s += __shfl_down_sync(0xffffffffu, s, off);
    if (lane == 0) out[gwarp] = sigm(s + bout[0]);
}

// ---------------- launch ----------------
extern "C" void kernel_launch(void* const* d_in, const int* in_sizes, int n_in,
                              void* d_out, int out_size) {
    const int*   tokens = (const int*)d_in[0];
    const float* emb    = (const float*)d_in[1];
    const float* W1     = (const float*)d_in[2];
    const float* U1     = (const float*)d_in[3];
    const float* b1     = (const float*)d_in[4];
    const float* W2     = (const float*)d_in[5];
    const float* U2     = (const float*)d_in[6];
    const float* b2     = (const float*)d_in[7];
    const float* Wout   = (const float*)d_in[8];
    const float* bout   = (const float*)d_in[9];
    float* out = (float*)d_out;

    zero_state<<<(BATCH * HSTR + 255) / 256, 256>>>();
    reorder_weights<<<(2 * UNITS * ZDIM + 255) / 256, 256>>>(U1, W2, U2, b2);
    embw1_kernel<<<dim3(ZDIM / 64, (VOCAB + 63) / 64), 256>>>(emb, W1, b1);

    dim3 sgrid(ZDIM / 128, BATCH / 128);   // 16 x 8 = 128 blocks
    int ping = 0;
    for (int t = 0; t < SEQ; ++t) {
        lstm_step<<<sgrid, 256>>>(tokens, t, ping, 0);
        lstm_step<<<sgrid, 256>>>(tokens, t, ping, 1);
        ping ^= 1;
    }
    out_kernel<<<BATCH * 32 / 256, 256>>>(Wout, bout, out, ping);
}

// round 6
// speedup vs baseline: 4.9822x; 4.9822x over previous
#include <cuda_runtime.h>
#include <cuda_bf16.h>
#include <cstdint>

#define VOCAB 10000
#define EMB   100
#define SEQ   80
#define BATCH 1024
#define UNITS 512
#define ZDIM  2048            // 4*UNITS
#define KP1   1536            // 3*512   (Hhi | Hlo | Hhi)
#define KP2   3072            // 3*1024

// ---------------- device scratch (static, no allocations) ----------------
__device__ float         g_EmbW1[(size_t)VOCAB * ZDIM];       // emb@W1+b1, natural cols (82MB)
__device__ __nv_bfloat16 g_B1[(size_t)ZDIM * KP1];            // [n][k]  (Whi|Whi|Wlo) of U1^T
__device__ __nv_bfloat16 g_B2[(size_t)ZDIM * KP2];            // [n][k]  of [W2;U2]^T
__device__ __nv_bfloat16 g_A1[2][(size_t)BATCH * KP1];        // [Hhi|Hlo|Hhi] of h1
__device__ __nv_bfloat16 g_A2[2][(size_t)BATCH * KP2];        // [h1hi h2hi | h1lo h2lo | h1hi h2hi]
__device__ float         g_C1[(size_t)BATCH * UNITS];
__device__ float         g_C2[(size_t)BATCH * UNITS];

// ---------------- helpers ----------------
__device__ __forceinline__ uint32_t smem_u32(const void* p) {
    uint32_t a;
    asm("{ .reg .u64 t; cvta.to.shared.u64 t, %1; cvt.u32.u64 %0, t; }" : "=r"(a) : "l"(p));
    return a;
}
__device__ __forceinline__ void cp16(uint32_t sa, const void* g) {
    asm volatile("cp.async.cg.shared.global [%0], [%1], 16;" :: "r"(sa), "l"(g));
}
#define CP_COMMIT() asm volatile("cp.async.commit_group;")

__device__ __forceinline__ void ldmA(uint32_t a, uint32_t* r) {
    asm volatile("ldmatrix.sync.aligned.m8n8.x4.shared.b16 {%0,%1,%2,%3}, [%4];"
                 : "=r"(r[0]), "=r"(r[1]), "=r"(r[2]), "=r"(r[3]) : "r"(a));
}
// B stored [n][k]: mem rows = n, mem cols = k == frag(row=lane>>2 -> n, colpair -> k): NO trans.
__device__ __forceinline__ void ldmB(uint32_t a, uint32_t* r) {
    asm volatile("ldmatrix.sync.aligned.m8n8.x2.shared.b16 {%0,%1}, [%2];"
                 : "=r"(r[0]), "=r"(r[1]) : "r"(a));
}
__device__ __forceinline__ void mma16816(float* c, const uint32_t* a, const uint32_t* b) {
    asm volatile("mma.sync.aligned.m16n8k16.row.col.f32.bf16.bf16.f32 "
                 "{%0,%1,%2,%3},{%4,%5,%6,%7},{%8,%9},{%0,%1,%2,%3};"
                 : "+f"(c[0]), "+f"(c[1]), "+f"(c[2]), "+f"(c[3])
                 : "r"(a[0]), "r"(a[1]), "r"(a[2]), "r"(a[3]), "r"(b[0]), "r"(b[1]));
}
__device__ __forceinline__ float sigm(float x) { return __fdividef(1.0f, 1.0f + __expf(-x)); }

// ---------------- init / prep ----------------
__global__ void zero_state() {
    size_t i = (size_t)blockIdx.x * blockDim.x + threadIdx.x;
    size_t stride = (size_t)gridDim.x * blockDim.x;
    for (size_t k = i; k < (size_t)BATCH * KP1; k += stride) { g_A1[0][k] = __nv_bfloat16(0.f); g_A1[1][k] = __nv_bfloat16(0.f); }
    for (size_t k = i; k < (size_t)BATCH * KP2; k += stride) { g_A2[0][k] = __nv_bfloat16(0.f); g_A2[1][k] = __nv_bfloat16(0.f); }
    for (size_t k = i; k < (size_t)BATCH * UNITS; k += stride) { g_C1[k] = 0.f; g_C2[k] = 0.f; }
}

__global__ void make_B1(const float* __restrict__ U1) {
    size_t i = (size_t)blockIdx.x * blockDim.x + threadIdx.x;
    if (i >= (size_t)ZDIM * KP1) return;
    int n = (int)(i / KP1), k = (int)(i % KP1);
    float w; bool lo = false;
    if (k < 512)       w = U1[k * ZDIM + n];
    else if (k < 1024) w = U1[(k - 512) * ZDIM + n];
    else             { w = U1[(k - 1024) * ZDIM + n]; lo = true; }
    __nv_bfloat16 hi = __float2bfloat16(w);
    g_B1[i] = lo ? __float2bfloat16(w - __bfloat162float(hi)) : hi;
}

__global__ void make_B2(const float* __restrict__ W2, const float* __restrict__ U2) {
    size_t i = (size_t)blockIdx.x * blockDim.x + threadIdx.x;
    if (i >= (size_t)ZDIM * KP2) return;
    int n = (int)(i / KP2), k = (int)(i % KP2);
    int kh = (k < 1024) ? k : ((k < 2048) ? k - 1024 : k - 2048);
    bool lo = (k >= 2048);
    float w = (kh < 512) ? W2[kh * ZDIM + n] : U2[(kh - 512) * ZDIM + n];
    __nv_bfloat16 hi = __float2bfloat16(w);
    g_B2[i] = lo ? __float2bfloat16(w - __bfloat162float(hi)) : hi;
}

// EmbW1[v][c] = sum_e emb[v][e]*W1[e][c] + b1[c]  (fp32)
__global__ __launch_bounds__(256) void embw1_kernel(const float* __restrict__ emb,
                                                    const float* __restrict__ W1,
                                                    const float* __restrict__ b1) {
    __shared__ float Ae[32][65];
    __shared__ float Be[32][64];
    int tid = threadIdx.x;
    int tx = tid & 15, ty = tid >> 4;
    int vBase = blockIdx.y * 64, cBase = blockIdx.x * 64;
    float acc[4][4];
#pragma unroll
    for (int i = 0; i < 4; ++i)
#pragma unroll
        for (int j = 0; j < 4; ++j) acc[i][j] = 0.0f;
    for (int kt = 0; kt < 4; ++kt) {
        {
            int vrow = tid >> 2, k0 = (tid & 3) * 8;
            int v = vBase + vrow;
#pragma unroll
            for (int j = 0; j < 8; ++j) {
                int k = kt * 32 + k0 + j;
                Ae[k0 + j][vrow] = (k < EMB && v < VOCAB) ? emb[v * EMB + k] : 0.0f;
            }
        }
        {
            int krow = tid >> 3, c0 = (tid & 7) * 8;
            int k = kt * 32 + krow;
#pragma unroll
            for (int j = 0; j < 8; ++j)
                Be[krow][c0 + j] = (k < EMB) ? W1[k * ZDIM + cBase + c0 + j] : 0.0f;
        }
        __syncthreads();
#pragma unroll
        for (int kk = 0; kk < 32; ++kk) {
            float a[4], b[4];
#pragma unroll
            for (int i = 0; i < 4; ++i) a[i] = Ae[kk][ty * 4 + i];
#pragma unroll
            for (int j = 0; j < 4; ++j) b[j] = Be[kk][tx * 4 + j];
#pragma unroll
            for (int i = 0; i < 4; ++i)
#pragma unroll
                for (int j = 0; j < 4; ++j) acc[i][j] = fmaf(a[i], b[j], acc[i][j]);
        }
        __syncthreads();
    }
#pragma unroll
    for (int i = 0; i < 4; ++i) {
        int v = vBase + ty * 4 + i;
        if (v >= VOCAB) continue;
#pragma unroll
        for (int j = 0; j < 4; ++j) {
            int c = cBase + tx * 4 + j;
            g_EmbW1[(size_t)v * ZDIM + c] = acc[i][j] + b1[c];
        }
    }
}

// ---------------- HMMA step kernel ----------------
// grid (16, 8): blockIdx.x = unit tile (32 units -> 128 z-cols across 4 gates),
//               blockIdx.y = batch row tile (128 rows). 256 threads = 8 warps (2x4).
// SMEM: double-buffered A/B tiles, BK=32 bf16, rows padded 64B->80B for ldmatrix.
#define ROWB 80

__global__ __launch_bounds__(256) void lstm_tc(const int* __restrict__ tokens,
                                               const float* __restrict__ b2,
                                               int t, int q, int p, int layer) {
    __shared__ __align__(128) char smA[2][128 * ROWB];
    __shared__ __align__(128) char smB[2][128 * ROWB];

    const int tid = threadIdx.x;
    const int wid = tid >> 5, lane = tid & 31;
    const int warp_m = wid >> 2, warp_n = wid & 3;

    const __nv_bfloat16 *Ag, *Bg;
    float* Cst;
    int KP;
    if (layer == 0) { Ag = g_A1[q]; Bg = g_B1; KP = KP1; Cst = g_C1; }
    else            { Ag = g_A2[p]; Bg = g_B2; KP = KP2; Cst = g_C2; }

    const int rowTile = blockIdx.y * 128;
    const int uTile = blockIdx.x * 32;
    const size_t strideBy = (size_t)KP * 2;  // bytes per row of A/B
    const char* Agc = (const char*)Ag;
    const char* Bgc = (const char*)Bg;

    const uint32_t sA0 = smem_u32(smA[0]), sA1 = smem_u32(smA[1]);
    const uint32_t sB0 = smem_u32(smB[0]), sB1 = smem_u32(smB[1]);

    // loader: 1024 cp16 per tile / 256 threads = 4 each
    // id in [0,1024): id>=512 -> B; idx=id&511: r=idx>>2, c=idx&3
    // A src row = rowTile + r;  B src row n = (r>>5)*512 + uTile + (r&31)
    int l_r[4], l_c[4];
    size_t l_aoff[4], l_boff[4];
#pragma unroll
    for (int i = 0; i < 4; ++i) {
        int id = i * 256 + tid;
        int idx = id & 511;
        l_r[i] = idx >> 2; l_c[i] = idx & 3;
        l_aoff[i] = (size_t)(rowTile + l_r[i]) * strideBy;
        int n = ((l_r[i] >> 5) * 512) + uTile + (l_r[i] & 31);
        l_boff[i] = (size_t)n * strideBy;
    }

    float acc[4][4][4];
#pragma unroll
    for (int mi = 0; mi < 4; ++mi)
#pragma unroll
        for (int g = 0; g < 4; ++g)
#pragma unroll
            for (int j = 0; j < 4; ++j) acc[mi][g][j] = 0.0f;

    // ldmatrix addresses
    const int a_row = warp_m * 64 + (lane & 7) + ((lane >> 3) & 1) * 8;   // + mi*16
    const int a_c16 = (lane >> 4) & 1;                                     // +16B for k-hi
    const int l15 = lane & 15;
    const int b_row = warp_n * 8 + (l15 & 7);                              // + g*32
    const int b_c16 = l15 >> 3;                                            // k-halves 0..7 / 8..15

    const int NT = KP >> 5;   // 32-k tiles

    // preload tile 0
#pragma unroll
    for (int i = 0; i < 4; ++i) {
        int id = i * 256 + tid;
        uint32_t so = (uint32_t)(l_r[i] * ROWB + l_c[i] * 16);
        if (id < 512) cp16(sA0 + so, Agc + l_aoff[i] + l_c[i] * 16);
        else          cp16(sB0 + so, Bgc + l_boff[i] + l_c[i] * 16);
    }
    CP_COMMIT();

    for (int kt = 0; kt < NT; ++kt) {
        int b = kt & 1;
        uint32_t sA = b ? sA1 : sA0;
        uint32_t sB = b ? sB1 : sB0;
        if (kt + 1 < NT) {
            uint32_t dA = b ? sA0 : sA1;
            uint32_t dB = b ? sB0 : sB1;
            size_t go = (size_t)(kt + 1) * 64;
#pragma unroll
            for (int i = 0; i < 4; ++i) {
                int id = i * 256 + tid;
                uint32_t so = (uint32_t)(l_r[i] * ROWB + l_c[i] * 16);
                if (id < 512) cp16(dA + so, Agc + l_aoff[i] + go + l_c[i] * 16);
                else          cp16(dB + so, Bgc + l_boff[i] + go + l_c[i] * 16);
            }
            CP_COMMIT();
            asm volatile("cp.async.wait_group 1;");
        } else {
            asm volatile("cp.async.wait_group 0;");
        }
        __syncthreads();

#pragma unroll
        for (int ks = 0; ks < 2; ++ks) {
            uint32_t af[4][4], bf[4][2];
#pragma unroll
            for (int mi = 0; mi < 4; ++mi)
                ldmA(sA + (uint32_t)((a_row + mi * 16) * ROWB + ks * 32 + a_c16 * 16), af[mi]);
#pragma unroll
            for (int g = 0; g < 4; ++g)
                ldmB(sB + (uint32_t)((b_row + g * 32) * ROWB + ks * 32 + b_c16 * 16), bf[g]);
#pragma unroll
            for (int mi = 0; mi < 4; ++mi)
#pragma unroll
                for (int g = 0; g < 4; ++g)
                    mma16816(acc[mi][g], af[mi], bf[g]);
        }
        __syncthreads();
    }

    // ---------------- epilogue: thread-local gates ----------------
    // thread owns rows: rowTile + warp_m*64 + mi*16 + (lane>>2) + h*8  (mi=0..3, h=0..1)
    //        and units: uTile + warp_n*8 + (lane&3)*2 + {0,1}  (all 4 gates in acc)
    const int u0 = uTile + warp_n * 8 + (lane & 3) * 2;
    __nv_bfloat16* d1;
    __nv_bfloat16* d2 = nullptr;
    if (layer == 0) { d1 = g_A1[q ^ 1]; d2 = g_A2[p]; }
    else            { d1 = g_A2[p ^ 1]; }

#pragma unroll
    for (int mi = 0; mi < 4; ++mi) {
#pragma unroll
        for (int h = 0; h < 2; ++h) {
            int row = rowTile + warp_m * 64 + mi * 16 + (lane >> 2) + h * 8;
            const float* Xrow;
            if (layer == 0) Xrow = g_EmbW1 + (size_t)tokens[row * SEQ + t] * ZDIM;
            else            Xrow = b2;
            float2 xz[4];
#pragma unroll
            for (int g = 0; g < 4; ++g) xz[g] = *(const float2*)(Xrow + g * 512 + u0);

            float zi0 = acc[mi][0][h * 2 + 0] + xz[0].x, zi1 = acc[mi][0][h * 2 + 1] + xz[0].y;
            float zf0 = acc[mi][1][h * 2 + 0] + xz[1].x, zf1 = acc[mi][1][h * 2 + 1] + xz[1].y;
            float zg0 = acc[mi][2][h * 2 + 0] + xz[2].x, zg1 = acc[mi][2][h * 2 + 1] + xz[2].y;
            float zo0 = acc[mi][3][h * 2 + 0] + xz[3].x, zo1 = acc[mi][3][h * 2 + 1] + xz[3].y;

            float* cp = Cst + (size_t)row * UNITS + u0;
            float2 c = *(float2*)cp;
            c.x = sigm(zf0) * c.x + sigm(zi0) * tanhf(zg0);
            c.y = sigm(zf1) * c.y + sigm(zi1) * tanhf(zg1);
            *(float2*)cp = c;
            float hv0 = sigm(zo0) * tanhf(c.x);
            float hv1 = sigm(zo1) * tanhf(c.y);

            __nv_bfloat16 bh0 = __float2bfloat16(hv0);
            __nv_bfloat16 bh1 = __float2bfloat16(hv1);
            __nv_bfloat16 bl0 = __float2bfloat16(hv0 - __bfloat162float(bh0));
            __nv_bfloat16 bl1 = __float2bfloat16(hv1 - __bfloat162float(bh1));
            uint32_t hiP = ((uint32_t)*(unsigned short*)&bh1 << 16) | *(unsigned short*)&bh0;
            uint32_t loP = ((uint32_t)*(unsigned short*)&bl1 << 16) | *(unsigned short*)&bl0;

            if (layer == 0) {
                __nv_bfloat16* a1 = d1 + (size_t)row * KP1;
                *(uint32_t*)(a1 + u0)        = hiP;
                *(uint32_t*)(a1 + 512 + u0)  = loP;
                *(uint32_t*)(a1 + 1024 + u0) = hiP;
                __nv_bfloat16* a2 = d2 + (size_t)row * KP2;
                *(uint32_t*)(a2 + u0)        = hiP;
                *(uint32_t*)(a2 + 1024 + u0) = loP;
                *(uint32_t*)(a2 + 2048 + u0) = hiP;
            } else {
                __nv_bfloat16* a2 = d1 + (size_t)row * KP2;
                *(uint32_t*)(a2 + 512 + u0)  = hiP;
                *(uint32_t*)(a2 + 1536 + u0) = loP;
                *(uint32_t*)(a2 + 2560 + u0) = hiP;
            }
        }
    }
}

// ---------------- output head ----------------
__global__ void out_kernel(const float* __restrict__ Wout, const float* __restrict__ bout,
                           float* __restrict__ out, int p) {
    const __nv_bfloat16* A2f = g_A2[p];
    int row = (blockIdx.x * blockDim.x + threadIdx.x) >> 5;
    int lane = threadIdx.x & 31;
    float s = 0.0f;
    for (int k = lane; k < UNITS; k += 32) {
        float h = __bfloat162float(A2f[(size_t)row * KP2 + 512 + k]) +
                  __bfloat162float(A2f[(size_t)row * KP2 + 1536 + k]);
        s += h * Wout[k];
    }
#pragma unroll
    for (int off = 16; off; off >>= 1) s += __shfl_down_sync(0xffffffffu, s, off);
    if (lane == 0) out[row] = sigm(s + bout[0]);
}

// ---------------- launch ----------------
extern "C" void kernel_launch(void* const* d_in, const int* in_sizes, int n_in,
                              void* d_out, int out_size) {
    const int*   tokens = (const int*)d_in[0];
    const float* emb    = (const float*)d_in[1];
    const float* W1     = (const float*)d_in[2];
    const float* U1     = (const float*)d_in[3];
    const float* b1     = (const float*)d_in[4];
    const float* W2     = (const float*)d_in[5];
    const float* U2     = (const float*)d_in[6];
    const float* b2     = (const float*)d_in[7];
    const float* Wout   = (const float*)d_in[8];
    const float* bout   = (const float*)d_in[9];
    float* out = (float*)d_out;

    zero_state<<<1024, 256>>>();
    make_B1<<<((size_t)ZDIM * KP1 + 255) / 256, 256>>>(U1);
    make_B2<<<((size_t)ZDIM * KP2 + 255) / 256, 256>>>(W2, U2);
    embw1_kernel<<<dim3(ZDIM / 64, (VOCAB + 63) / 64), 256>>>(emb, W1, b1);

    dim3 grid(16, 8);   // unit tiles x batch tiles = 128 CTAs
    int q = 0, p = 0;
    for (int t = 0; t < SEQ; ++t) {
        lstm_tc<<<grid, 256>>>(tokens, b2, t, q, p, 0);
        lstm_tc<<<grid, 256>>>(tokens, b2, t, q, p, 1);
        q ^= 1; p ^= 1;
    }
    out_kernel<<<BATCH / 8, 256>>>(Wout, bout, out, p);
}

// round 7
// speedup vs baseline: 11.5229x; 2.3128x over previous
#include <cuda_runtime.h>
#include <cuda_bf16.h>
#include <cstdint>

#define VOCAB 10000
#define EMB   100
#define SEQ   80
#define BATCH 1024
#define UNITS 512
#define ZDIM  2048            // 4*UNITS
#define K1    512             // layer1 K (pure bf16, no split)
#define K2    1024            // layer2 K ([h1|h2])

// ---------------- device scratch (static, no allocations) ----------------
__device__ float         g_EmbW1[(size_t)VOCAB * ZDIM];       // emb@W1+b1, natural cols (82MB)
__device__ __nv_bfloat16 g_B1[(size_t)ZDIM * K1];             // [n][k]  U1^T  bf16
__device__ __nv_bfloat16 g_B2[(size_t)ZDIM * K2];             // [n][k]  [W2;U2]^T bf16
__device__ __nv_bfloat16 g_A1[2][(size_t)BATCH * K1];         // h1 bf16, ping-pong
__device__ __nv_bfloat16 g_A2[2][(size_t)BATCH * K2];         // [h1 | h2] bf16, ping-pong
__device__ float         g_H2f[(size_t)BATCH * UNITS];        // fp32 h2 for output head
__device__ float         g_C1[(size_t)BATCH * UNITS];
__device__ float         g_C2[(size_t)BATCH * UNITS];

// ---------------- helpers ----------------
__device__ __forceinline__ uint32_t smem_u32(const void* p) {
    uint32_t a;
    asm("{ .reg .u64 t; cvta.to.shared.u64 t, %1; cvt.u32.u64 %0, t; }" : "=r"(a) : "l"(p));
    return a;
}
__device__ __forceinline__ void cp16(uint32_t sa, const void* g) {
    asm volatile("cp.async.cg.shared.global [%0], [%1], 16;" :: "r"(sa), "l"(g));
}
#define CP_COMMIT() asm volatile("cp.async.commit_group;")

__device__ __forceinline__ void ldmA(uint32_t a, uint32_t* r) {
    asm volatile("ldmatrix.sync.aligned.m8n8.x4.shared.b16 {%0,%1,%2,%3}, [%4];"
                 : "=r"(r[0]), "=r"(r[1]), "=r"(r[2]), "=r"(r[3]) : "r"(a));
}
// B stored [n][k]: frag(row=lane>>2 -> n, colpair -> k): NO trans (verified R5).
__device__ __forceinline__ void ldmB(uint32_t a, uint32_t* r) {
    asm volatile("ldmatrix.sync.aligned.m8n8.x2.shared.b16 {%0,%1}, [%2];"
                 : "=r"(r[0]), "=r"(r[1]) : "r"(a));
}
__device__ __forceinline__ void mma16816(float* c, const uint32_t* a, const uint32_t* b) {
    asm volatile("mma.sync.aligned.m16n8k16.row.col.f32.bf16.bf16.f32 "
                 "{%0,%1,%2,%3},{%4,%5,%6,%7},{%8,%9},{%0,%1,%2,%3};"
                 : "+f"(c[0]), "+f"(c[1]), "+f"(c[2]), "+f"(c[3])
                 : "r"(a[0]), "r"(a[1]), "r"(a[2]), "r"(a[3]), "r"(b[0]), "r"(b[1]));
}
__device__ __forceinline__ float sigm(float x) { return __fdividef(1.0f, 1.0f + __expf(-x)); }

// ---------------- init / prep ----------------
__global__ void zero_state() {
    size_t i = (size_t)blockIdx.x * blockDim.x + threadIdx.x;
    size_t stride = (size_t)gridDim.x * blockDim.x;
    for (size_t k = i; k < (size_t)BATCH * K1; k += stride) { g_A1[0][k] = __nv_bfloat16(0.f); g_A1[1][k] = __nv_bfloat16(0.f); }
    for (size_t k = i; k < (size_t)BATCH * K2; k += stride) { g_A2[0][k] = __nv_bfloat16(0.f); g_A2[1][k] = __nv_bfloat16(0.f); }
    for (size_t k = i; k < (size_t)BATCH * UNITS; k += stride) { g_C1[k] = 0.f; g_C2[k] = 0.f; }
}

__global__ void make_B1(const float* __restrict__ U1) {
    size_t i = (size_t)blockIdx.x * blockDim.x + threadIdx.x;
    if (i >= (size_t)ZDIM * K1) return;
    int n = (int)(i / K1), k = (int)(i % K1);
    g_B1[i] = __float2bfloat16(U1[k * ZDIM + n]);
}

__global__ void make_B2(const float* __restrict__ W2, const float* __restrict__ U2) {
    size_t i = (size_t)blockIdx.x * blockDim.x + threadIdx.x;
    if (i >= (size_t)ZDIM * K2) return;
    int n = (int)(i / K2), k = (int)(i % K2);
    float w = (k < 512) ? W2[k * ZDIM + n] : U2[(k - 512) * ZDIM + n];
    g_B2[i] = __float2bfloat16(w);
}

// EmbW1[v][c] = sum_e emb[v][e]*W1[e][c] + b1[c]  (fp32)
__global__ __launch_bounds__(256) void embw1_kernel(const float* __restrict__ emb,
                                                    const float* __restrict__ W1,
                                                    const float* __restrict__ b1) {
    __shared__ float Ae[32][65];
    __shared__ float Be[32][64];
    int tid = threadIdx.x;
    int tx = tid & 15, ty = tid >> 4;
    int vBase = blockIdx.y * 64, cBase = blockIdx.x * 64;
    float acc[4][4];
#pragma unroll
    for (int i = 0; i < 4; ++i)
#pragma unroll
        for (int j = 0; j < 4; ++j) acc[i][j] = 0.0f;
    for (int kt = 0; kt < 4; ++kt) {
        {
            int vrow = tid >> 2, k0 = (tid & 3) * 8;
            int v = vBase + vrow;
#pragma unroll
            for (int j = 0; j < 8; ++j) {
                int k = kt * 32 + k0 + j;
                Ae[k0 + j][vrow] = (k < EMB && v < VOCAB) ? emb[v * EMB + k] : 0.0f;
            }
        }
        {
            int krow = tid >> 3, c0 = (tid & 7) * 8;
            int k = kt * 32 + krow;
#pragma unroll
            for (int j = 0; j < 8; ++j)
                Be[krow][c0 + j] = (k < EMB) ? W1[k * ZDIM + cBase + c0 + j] : 0.0f;
        }
        __syncthreads();
#pragma unroll
        for (int kk = 0; kk < 32; ++kk) {
            float a[4], b[4];
#pragma unroll
            for (int i = 0; i < 4; ++i) a[i] = Ae[kk][ty * 4 + i];
#pragma unroll
            for (int j = 0; j < 4; ++j) b[j] = Be[kk][tx * 4 + j];
#pragma unroll
            for (int i = 0; i < 4; ++i)
#pragma unroll
                for (int j = 0; j < 4; ++j) acc[i][j] = fmaf(a[i], b[j], acc[i][j]);
        }
        __syncthreads();
    }
#pragma unroll
    for (int i = 0; i < 4; ++i) {
        int v = vBase + ty * 4 + i;
        if (v >= VOCAB) continue;
#pragma unroll
        for (int j = 0; j < 4; ++j) {
            int c = cBase + tx * 4 + j;
            g_EmbW1[(size_t)v * ZDIM + c] = acc[i][j] + b1[c];
        }
    }
}

// ---------------- HMMA step kernel ----------------
// grid (16, 8): blockIdx.x = unit tile (32 units -> 128 z-cols across 4 gates),
//               blockIdx.y = batch row tile (128 rows). 256 threads = 8 warps (2x4).
// SMEM: double-buffered A/B tiles, BK=32 bf16, rows padded 64B->80B for ldmatrix.
#define ROWB 80

__global__ __launch_bounds__(256) void lstm_tc(const int* __restrict__ tokens,
                                               const float* __restrict__ b2,
                                               int t, int q, int p, int layer) {
    __shared__ __align__(128) char smA[2][128 * ROWB];
    __shared__ __align__(128) char smB[2][128 * ROWB];

    const int tid = threadIdx.x;
    const int wid = tid >> 5, lane = tid & 31;
    const int warp_m = wid >> 2, warp_n = wid & 3;

    const __nv_bfloat16 *Ag, *Bg;
    float* Cst;
    int KP;
    if (layer == 0) { Ag = g_A1[q]; Bg = g_B1; KP = K1; Cst = g_C1; }
    else            { Ag = g_A2[p]; Bg = g_B2; KP = K2; Cst = g_C2; }

    const int rowTile = blockIdx.y * 128;
    const int uTile = blockIdx.x * 32;
    const size_t strideBy = (size_t)KP * 2;  // bytes per row of A/B
    const char* Agc = (const char*)Ag;
    const char* Bgc = (const char*)Bg;

    const uint32_t sA0 = smem_u32(smA[0]), sA1 = smem_u32(smA[1]);
    const uint32_t sB0 = smem_u32(smB[0]), sB1 = smem_u32(smB[1]);

    // loader: 1024 cp16 per tile / 256 threads = 4 each
    // id in [0,1024): id>=512 -> B; idx=id&511: r=idx>>2, c=idx&3
    // A src row = rowTile + r;  B src row n = (r>>5)*512 + uTile + (r&31)
    int l_r[4], l_c[4];
    size_t l_aoff[4], l_boff[4];
#pragma unroll
    for (int i = 0; i < 4; ++i) {
        int id = i * 256 + tid;
        int idx = id & 511;
        l_r[i] = idx >> 2; l_c[i] = idx & 3;
        l_aoff[i] = (size_t)(rowTile + l_r[i]) * strideBy;
        int n = ((l_r[i] >> 5) * 512) + uTile + (l_r[i] & 31);
        l_boff[i] = (size_t)n * strideBy;
    }

    float acc[4][4][4];
#pragma unroll
    for (int mi = 0; mi < 4; ++mi)
#pragma unroll
        for (int g = 0; g < 4; ++g)
#pragma unroll
            for (int j = 0; j < 4; ++j) acc[mi][g][j] = 0.0f;

    // ldmatrix addresses
    const int a_row = warp_m * 64 + (lane & 7) + ((lane >> 3) & 1) * 8;   // + mi*16
    const int a_c16 = (lane >> 4) & 1;                                     // +16B for k-hi
    const int l15 = lane & 15;
    const int b_row = warp_n * 8 + (l15 & 7);                              // + g*32
    const int b_c16 = l15 >> 3;                                            // k-halves 0..7 / 8..15

    const int NT = KP >> 5;   // 32-k tiles: 16 (layer1) / 32 (layer2)

    // preload tile 0
#pragma unroll
    for (int i = 0; i < 4; ++i) {
        int id = i * 256 + tid;
        uint32_t so = (uint32_t)(l_r[i] * ROWB + l_c[i] * 16);
        if (id < 512) cp16(sA0 + so, Agc + l_aoff[i] + l_c[i] * 16);
        else          cp16(sB0 + so, Bgc + l_boff[i] + l_c[i] * 16);
    }
    CP_COMMIT();

    for (int kt = 0; kt < NT; ++kt) {
        int b = kt & 1;
        uint32_t sA = b ? sA1 : sA0;
        uint32_t sB = b ? sB1 : sB0;
        if (kt + 1 < NT) {
            uint32_t dA = b ? sA0 : sA1;
            uint32_t dB = b ? sB0 : sB1;
            size_t go = (size_t)(kt + 1) * 64;
#pragma unroll
            for (int i = 0; i < 4; ++i) {
                int id = i * 256 + tid;
                uint32_t so = (uint32_t)(l_r[i] * ROWB + l_c[i] * 16);
                if (id < 512) cp16(dA + so, Agc + l_aoff[i] + go + l_c[i] * 16);
                else          cp16(dB + so, Bgc + l_boff[i] + go + l_c[i] * 16);
            }
            CP_COMMIT();
            asm volatile("cp.async.wait_group 1;");
        } else {
            asm volatile("cp.async.wait_group 0;");
        }
        __syncthreads();

#pragma unroll
        for (int ks = 0; ks < 2; ++ks) {
            uint32_t af[4][4], bf[4][2];
#pragma unroll
            for (int mi = 0; mi < 4; ++mi)
                ldmA(sA + (uint32_t)((a_row + mi * 16) * ROWB + ks * 32 + a_c16 * 16), af[mi]);
#pragma unroll
            for (int g = 0; g < 4; ++g)
                ldmB(sB + (uint32_t)((b_row + g * 32) * ROWB + ks * 32 + b_c16 * 16), bf[g]);
#pragma unroll
            for (int mi = 0; mi < 4; ++mi)
#pragma unroll
                for (int g = 0; g < 4; ++g)
                    mma16816(acc[mi][g], af[mi], bf[g]);
        }
        __syncthreads();
    }

    // ---------------- epilogue: thread-local gates ----------------
    // thread owns rows: rowTile + warp_m*64 + mi*16 + (lane>>2) + h*8  (mi=0..3, h=0..1)
    //        and units: uTile + warp_n*8 + (lane&3)*2 + {0,1}  (all 4 gates in acc)
    const int u0 = uTile + warp_n * 8 + (lane & 3) * 2;
    __nv_bfloat16* d1;
    __nv_bfloat16* d2 = nullptr;
    if (layer == 0) { d1 = g_A1[q ^ 1]; d2 = g_A2[p]; }
    else            { d1 = g_A2[p ^ 1]; }

#pragma unroll
    for (int mi = 0; mi < 4; ++mi) {
#pragma unroll
        for (int h = 0; h < 2; ++h) {
            int row = rowTile + warp_m * 64 + mi * 16 + (lane >> 2) + h * 8;
            const float* Xrow;
            if (layer == 0) Xrow = g_EmbW1 + (size_t)tokens[row * SEQ + t] * ZDIM;
            else            Xrow = b2;
            float2 xz[4];
#pragma unroll
            for (int g = 0; g < 4; ++g) xz[g] = *(const float2*)(Xrow + g * 512 + u0);

            float zi0 = acc[mi][0][h * 2 + 0] + xz[0].x, zi1 = acc[mi][0][h * 2 + 1] + xz[0].y;
            float zf0 = acc[mi][1][h * 2 + 0] + xz[1].x, zf1 = acc[mi][1][h * 2 + 1] + xz[1].y;
            float zg0 = acc[mi][2][h * 2 + 0] + xz[2].x, zg1 = acc[mi][2][h * 2 + 1] + xz[2].y;
            float zo0 = acc[mi][3][h * 2 + 0] + xz[3].x, zo1 = acc[mi][3][h * 2 + 1] + xz[3].y;

            float* cp = Cst + (size_t)row * UNITS + u0;
            float2 c = *(float2*)cp;
            c.x = sigm(zf0) * c.x + sigm(zi0) * tanhf(zg0);
            c.y = sigm(zf1) * c.y + sigm(zi1) * tanhf(zg1);
            *(float2*)cp = c;
            float hv0 = sigm(zo0) * tanhf(c.x);
            float hv1 = sigm(zo1) * tanhf(c.y);

            __nv_bfloat16 bh0 = __float2bfloat16(hv0);
            __nv_bfloat16 bh1 = __float2bfloat16(hv1);
            uint32_t hiP = ((uint32_t)*(unsigned short*)&bh1 << 16) | *(unsigned short*)&bh0;

            if (layer == 0) {
                *(uint32_t*)(d1 + (size_t)row * K1 + u0) = hiP;          // h1 -> A1[q^1]
                *(uint32_t*)(d2 + (size_t)row * K2 + u0) = hiP;          // h1 -> A2[p] (h1 part)
            } else {
                *(uint32_t*)(d1 + (size_t)row * K2 + 512 + u0) = hiP;    // h2 -> A2[p^1] (h2 part)
                *(float2*)(g_H2f + (size_t)row * UNITS + u0) = make_float2(hv0, hv1);
            }
        }
    }
}

// ---------------- output head ----------------
__global__ void out_kernel(const float* __restrict__ Wout, const float* __restrict__ bout,
                           float* __restrict__ out) {
    int row = (blockIdx.x * blockDim.x + threadIdx.x) >> 5;
    int lane = threadIdx.x & 31;
    float s = 0.0f;
    for (int k = lane; k < UNITS; k += 32)
        s += g_H2f[(size_t)row * UNITS + k] * Wout[k];
#pragma unroll
    for (int off = 16; off; off >>= 1) s += __shfl_down_sync(0xffffffffu, s, off);
    if (lane == 0) out[row] = sigm(s + bout[0]);
}

// ---------------- launch ----------------
extern "C" void kernel_launch(void* const* d_in, const int* in_sizes, int n_in,
                              void* d_out, int out_size) {
    const int*   tokens = (const int*)d_in[0];
    const float* emb    = (const float*)d_in[1];
    const float* W1     = (const float*)d_in[2];
    const float* U1     = (const float*)d_in[3];
    const float* b1     = (const float*)d_in[4];
    const float* W2     = (const float*)d_in[5];
    const float* U2     = (const float*)d_in[6];
    const float* b2     = (const float*)d_in[7];
    const float* Wout   = (const float*)d_in[8];
    const float* bout   = (const float*)d_in[9];
    float* out = (float*)d_out;

    zero_state<<<1024, 256>>>();
    make_B1<<<((size_t)ZDIM * K1 + 255) / 256, 256>>>(U1);
    make_B2<<<((size_t)ZDIM * K2 + 255) / 256, 256>>>(W2, U2);
    embw1_kernel<<<dim3(ZDIM / 64, (VOCAB + 63) / 64), 256>>>(emb, W1, b1);

    dim3 grid(16, 8);   // unit tiles x batch tiles = 128 CTAs
    int q = 0, p = 0;
    for (int t = 0; t < SEQ; ++t) {
        lstm_tc<<<grid, 256>>>(tokens, b2, t, q, p, 0);
        lstm_tc<<<grid, 256>>>(tokens, b2, t, q, p, 1);
        q ^= 1; p ^= 1;
    }
    out_kernel<<<BATCH / 8, 256>>>(Wout, bout, out);
}